// round 13
// baseline (speedup 1.0000x reference)
#include <cuda_runtime.h>
#include <cuda_bf16.h>
#include <cstdint>
#include <cmath>

#define BATCH 8
#define CH    512
#define NTOK  4096

// ---------------- scratch (device globals) ----------------
__device__ __nv_bfloat16 g_Wt[4 * CH * CH];           // transposed bf16 weights [c][d]
__device__ __nv_bfloat16 g_X [3 * BATCH * CH * NTOK]; // bf16 q,k,v in [b][c][n]
__device__ __nv_bfloat16 g_Q [BATCH * CH * NTOK];
__device__ __nv_bfloat16 g_K [BATCH * CH * NTOK];
__device__ __nv_bfloat16 g_V [BATCH * CH * NTOK];
__device__ __nv_bfloat16 g_M [BATCH * CH * NTOK];
__device__ float g_Ksum[BATCH * CH];

// ---------------- helpers ----------------
__device__ __forceinline__ uint32_t smem_u32(const void* p) {
    uint32_t a;
    asm("{ .reg .u64 t; cvta.to.shared.u64 t, %1; cvt.u32.u64 %0, t; }" : "=r"(a) : "l"(p));
    return a;
}
__device__ __forceinline__ uint32_t bf2u(__nv_bfloat162 h) {
    union { __nv_bfloat162 h; uint32_t u; } z; z.h = h; return z.u;
}
__device__ __forceinline__ void mma_bf16(float c[4], const uint32_t a[4], const uint32_t b[2]) {
    asm volatile(
        "mma.sync.aligned.m16n8k16.row.col.f32.bf16.bf16.f32 "
        "{%0,%1,%2,%3}, {%4,%5,%6,%7}, {%8,%9}, {%0,%1,%2,%3};"
        : "+f"(c[0]), "+f"(c[1]), "+f"(c[2]), "+f"(c[3])
        : "r"(a[0]), "r"(a[1]), "r"(a[2]), "r"(a[3]), "r"(b[0]), "r"(b[1]));
}
__device__ __forceinline__ void ldsm_x4(uint32_t r[4], uint32_t addr) {
    asm volatile("ldmatrix.sync.aligned.m8n8.x4.shared.b16 {%0,%1,%2,%3}, [%4];"
                 : "=r"(r[0]), "=r"(r[1]), "=r"(r[2]), "=r"(r[3]) : "r"(addr));
}
__device__ __forceinline__ void ldsm_x4_t(uint32_t r[4], uint32_t addr) {
    asm volatile("ldmatrix.sync.aligned.m8n8.x4.trans.shared.b16 {%0,%1,%2,%3}, [%4];"
                 : "=r"(r[0]), "=r"(r[1]), "=r"(r[2]), "=r"(r[3]) : "r"(addr));
}
#define CP16(dst, src) \
    asm volatile("cp.async.cg.shared.global [%0], [%1], 16;" :: "r"(dst), "l"(src) : "memory")
#define CP_COMMIT() asm volatile("cp.async.commit_group;" ::: "memory")
#define CP_WAIT(n)  asm volatile("cp.async.wait_group %0;" :: "n"(n) : "memory")

// packed f32x2 ops (sm_100+ base PTX)
__device__ __forceinline__ void fma2(unsigned long long& acc,
                                     unsigned long long a, unsigned long long b) {
    asm("fma.rn.f32x2 %0, %1, %2, %0;" : "+l"(acc) : "l"(a), "l"(b));
}
__device__ __forceinline__ unsigned long long bfpair_f32x2(uint32_t v) {
    union { uint32_t u; __nv_bfloat162 h; } z; z.u = v;
    float2 f = __bfloat1622float2(z.h);
    unsigned long long r;
    asm("mov.b64 %0, {%1, %2};" : "=l"(r) : "f"(f.x), "f"(f.y));
    return r;
}
// pack two f32 -> bf16x2 (lo = a, hi = b)
__device__ __forceinline__ uint32_t packbf(float a, float b) {
    uint32_t r;
    asm("cvt.rn.bf16x2.f32 %0, %1, %2;" : "=r"(r) : "f"(b), "f"(a));
    return r;
}

// =====================================================================
// weight prep: W fp32 [d][c] -> bf16 [c][d]  (grid 16,16,4); also zeros g_Ksum
// =====================================================================
__global__ __launch_bounds__(256) void wprep(
    const float* __restrict__ W0, const float* __restrict__ W1,
    const float* __restrict__ W2, const float* __restrict__ W3,
    __nv_bfloat16* __restrict__ D)
{
    __shared__ float t[32][33];
    if (blockIdx.z == 0 && blockIdx.y == 0)
        g_Ksum[blockIdx.x * 256 + threadIdx.x] = 0.f;
    const int z = blockIdx.z;
    const float* S = (z == 0) ? W0 : (z == 1) ? W1 : (z == 2) ? W2 : W3;
    __nv_bfloat16* Dz = D + (size_t)z * CH * CH;
    const int d0 = blockIdx.x * 32, c0 = blockIdx.y * 32;
    const int x = threadIdx.x & 31, y = threadIdx.x >> 5;
#pragma unroll
    for (int i = 0; i < 4; i++)
        t[y + 8 * i][x] = S[(size_t)(d0 + y + 8 * i) * CH + c0 + x];
    __syncthreads();
    const int m2 = threadIdx.x & 15, r0 = threadIdx.x >> 4;
#pragma unroll
    for (int i = 0; i < 2; i++) {
        const int r = r0 + 16 * i;
        __nv_bfloat162 h = __float22bfloat162_rn(make_float2(t[m2 * 2][r], t[m2 * 2 + 1][r]));
        *(__nv_bfloat162*)&Dz[(size_t)(c0 + r) * CH + d0 + m2 * 2] = h;
    }
}

// =====================================================================
// input prep: fp32 -> bf16 elementwise (grid 8192,1,3)
// =====================================================================
__global__ __launch_bounds__(256) void xconv(
    const float4* __restrict__ s0, const float4* __restrict__ s1,
    const float4* __restrict__ s2, uint4* __restrict__ d)
{
    const int z = blockIdx.z;
    const float4* s = (z == 0) ? s0 : (z == 1) ? s1 : s2;
    uint4* dz = d + (size_t)z * (BATCH * CH * NTOK / 8);
    const size_t i = (size_t)blockIdx.x * 256 + threadIdx.x;
    float4 a = s[2 * i], b = s[2 * i + 1];
    uint4 o;
    o.x = bf2u(__float22bfloat162_rn(make_float2(a.x, a.y)));
    o.y = bf2u(__float22bfloat162_rn(make_float2(a.z, a.w)));
    o.z = bf2u(__float22bfloat162_rn(make_float2(b.x, b.y)));
    o.w = bf2u(__float22bfloat162_rn(make_float2(b.z, b.w)));
    dz[i] = o;
}

// =====================================================================
// GEMM: C[b,d,n] = sum_c At[c,d] * B[b,c,n]  (+elu+1 | +bias | +ksum atomics)
// BM=BN=128, BK=32, 4-stage cp.async, 256 thr, 8 warps (4m x 2n), 32x64.
// (unchanged from validated baseline)
// =====================================================================
#define STG_SZ 16384
#define GEMM_SMEM (4 * STG_SZ)

template<bool PROJ, typename OutT, bool BIAS>
__global__ __launch_bounds__(256, 2) void gemm_ca(
    const __nv_bfloat16* __restrict__ A0, const __nv_bfloat16* __restrict__ A1,
    const __nv_bfloat16* __restrict__ A2,
    const __nv_bfloat16* __restrict__ X0, const __nv_bfloat16* __restrict__ X1,
    const __nv_bfloat16* __restrict__ X2,
    void* C0, void* C1, void* C2, const float* __restrict__ bias)
{
    extern __shared__ char smem[];
    const uint32_t sb = smem_u32(smem);

    int b; bool elu; int which = 0;
    const __nv_bfloat16 *A, *B; OutT* C;
    if (PROJ) {
        which = blockIdx.z >> 3; b = blockIdx.z & 7;
        A = (which == 0) ? A0 : (which == 1) ? A1 : A2;
        B = (which == 0) ? X0 : (which == 1) ? X1 : X2;
        C = (OutT*)((which == 0) ? C0 : (which == 1) ? C1 : C2);
        elu = (which < 2);
    } else {
        b = blockIdx.z; A = A0; B = X0; C = (OutT*)C0; elu = false;
    }

    const int m0 = blockIdx.y * 128, n0 = blockIdx.x * 128;
    const __nv_bfloat16* Bb = B + (size_t)b * CH * NTOK;
    OutT* Cb = C + (size_t)b * CH * NTOK;

    const int tid = threadIdx.x;
    const int lane = tid & 31, wid = tid >> 5;
    const int wm = wid & 3, wn = wid >> 2;
    const int gr = lane >> 2, kc = lane & 3;

    const int lr = tid >> 3;
    const int lc = (tid & 7) * 2;
    const int swz = lr & 7;

    const int klow = ((lane >> 3) & 1) * 8 + (lane & 7);
    const int cg   = lane >> 4;

    float acc[2][8][4];
#pragma unroll
    for (int i = 0; i < 2; i++)
#pragma unroll
        for (int j = 0; j < 8; j++)
#pragma unroll
            for (int r = 0; r < 4; r++) acc[i][j][r] = 0.f;

    auto issue = [&](int kt, int s) {
        const __nv_bfloat16* pa = A  + (size_t)(kt * 32 + lr) * CH   + m0 + lc * 8;
        const __nv_bfloat16* pb = Bb + (size_t)(kt * 32 + lr) * NTOK + n0 + lc * 8;
        const uint32_t base = sb + s * STG_SZ + lr * 256;
        CP16(base + ((lc     ^ swz) * 16),        pa);
        CP16(base + (((lc+1) ^ swz) * 16),        pa + 8);
        CP16(base + ((lc     ^ swz) * 16) + 8192, pb);
        CP16(base + (((lc+1) ^ swz) * 16) + 8192, pb + 8);
    };

#pragma unroll
    for (int s = 0; s < 3; s++) { issue(s, s); CP_COMMIT(); }

    const int KT = CH / 32;  // 16
#pragma unroll 1
    for (int kt = 0; kt < KT; ++kt) {
        CP_WAIT(2);
        __syncthreads();
        const int s = kt & 3;
        const uint32_t stA = sb + s * STG_SZ;

#pragma unroll
        for (int ks = 0; ks < 2; ++ks) {
            const int krow = ks * 16 + klow;
            const int kx = krow & 7;
            const uint32_t rb = stA + krow * 256;

            uint32_t af[2][4];
#pragma unroll
            for (int i = 0; i < 2; i++) {
                const int mc = wm * 4 + i * 2 + cg;
                uint32_t r[4];
                ldsm_x4_t(r, rb + ((mc ^ kx) * 16));
                af[i][0] = r[0]; af[i][1] = r[2]; af[i][2] = r[1]; af[i][3] = r[3];
            }
            uint32_t bf[8][2];
#pragma unroll
            for (int jj = 0; jj < 4; jj++) {
                const int nc = wn * 8 + jj * 2 + cg;
                uint32_t r[4];
                ldsm_x4_t(r, rb + 8192 + ((nc ^ kx) * 16));
                bf[jj * 2][0]     = r[0];
                bf[jj * 2][1]     = r[1];
                bf[jj * 2 + 1][0] = r[2];
                bf[jj * 2 + 1][1] = r[3];
            }
#pragma unroll
            for (int i = 0; i < 2; i++)
#pragma unroll
                for (int j = 0; j < 8; j++)
                    mma_bf16(acc[i][j], af[i], bf[j]);
        }

        if (kt + 3 < KT) issue(kt + 3, (kt + 3) & 3);
        CP_COMMIT();
    }

    // epilogue (+ fused Ksum for which==1)
#pragma unroll
    for (int i = 0; i < 2; i++) {
        const int row = m0 + wm * 32 + i * 16 + gr;
        const float bi0 = BIAS ? bias[row] : 0.f;
        const float bi1 = BIAS ? bias[row + 8] : 0.f;
        float rs0 = 0.f, rs1 = 0.f;
#pragma unroll
        for (int j = 0; j < 8; j++) {
            const int col = n0 + wn * 64 + j * 8 + kc * 2;
            float c0 = acc[i][j][0], c1 = acc[i][j][1];
            float c2 = acc[i][j][2], c3 = acc[i][j][3];
            if (PROJ && elu) {
                c0 = (c0 > 0.f) ? (c0 + 1.f) : __expf(c0);
                c1 = (c1 > 0.f) ? (c1 + 1.f) : __expf(c1);
                c2 = (c2 > 0.f) ? (c2 + 1.f) : __expf(c2);
                c3 = (c3 > 0.f) ? (c3 + 1.f) : __expf(c3);
            }
            if (BIAS) { c0 += bi0; c1 += bi0; c2 += bi1; c3 += bi1; }
            if (PROJ && which == 1) { rs0 += c0 + c1; rs1 += c2 + c3; }
            if constexpr (sizeof(OutT) == 2) {
                *(__nv_bfloat162*)&Cb[(size_t)row * NTOK + col] =
                    __float22bfloat162_rn(make_float2(c0, c1));
                *(__nv_bfloat162*)&Cb[(size_t)(row + 8) * NTOK + col] =
                    __float22bfloat162_rn(make_float2(c2, c3));
            } else {
                *(float2*)&Cb[(size_t)row * NTOK + col]       = make_float2(c0, c1);
                *(float2*)&Cb[(size_t)(row + 8) * NTOK + col] = make_float2(c2, c3);
            }
        }
        if (PROJ && which == 1) {
            rs0 += __shfl_xor_sync(0xffffffffu, rs0, 1);
            rs0 += __shfl_xor_sync(0xffffffffu, rs0, 2);
            rs1 += __shfl_xor_sync(0xffffffffu, rs1, 1);
            rs1 += __shfl_xor_sync(0xffffffffu, rs1, 2);
            if (kc == 0) {
                atomicAdd(&g_Ksum[b * CH + row],     rs0);
                atomicAdd(&g_Ksum[b * CH + row + 8], rs1);
            }
        }
    }
}

// =====================================================================
// Middle stage, tensor-core edition v4: 16 tokens/block, 512 threads.
// Change vs v3: O staging OVERLAYS the Q region (written only after the
// last Q read, separated by a block barrier) -> smem 87.5KB -> 69.1KB
// -> 3 CTAs/SM. All addressing/bank properties preserved.
// =====================================================================
#define QK_STR 80
#define QK_TOK 1280
#define VT_STR 48
#define VT_TOK 1536
#define GRP    32832         // Q(10240)+K(10240)+V(12288)=32768, +64 pad (bank shift)
#define GOFF_K 10240
#define GOFF_V 20480
#define GOFF_O 0             // O overlays Q
#define OFF_Z  (2 * GRP)                 // 65664; 16 tokens * 17 floats
#define OFF_KS (OFF_Z + 16 * 17 * 4)     // 66752; 16 * 36 floats
#define MID_SMEM (OFF_KS + 16 * 36 * 4)  // 69056

__device__ __forceinline__ int sigma_o(int c2) {
    return (c2 & 3) | (((c2 >> 4) & 7) << 2) | (((c2 >> 2) & 3) << 5) | (((c2 >> 7) & 1) << 7);
}

__global__ __launch_bounds__(512) void mid_kernel()
{
    extern __shared__ char smraw[];
    const uint32_t sb = smem_u32(smraw);
    float* Zs  = (float*)(smraw + OFF_Z);
    float* Ksm = (float*)(smraw + OFF_KS);

    const int blk = blockIdx.x;              // BATCH * 256
    const int b   = blk >> 8;
    const int n0  = (blk & 255) * 16;
    const size_t base = (size_t)b * CH * NTOK + n0;
    const int tid = threadIdx.x;
    const int l   = tid & 31;
    const int w   = tid >> 5;                // 0..15

    // ---- load phase ----
    {
        const int s  = l >> 1;               // 0..15
        const int hh = l & 1;                // token group (tokens hh*8 .. hh*8+7)
        char* grp = smraw + hh * GRP;

        // Q, K: thread owns c2 = w*16 + s (c rows 2*c2, 2*c2+1); h = w, d = 2s
        const int c2 = w * 16 + s;
        const size_t rA = base + (size_t)(2 * c2) * NTOK + hh * 8;
        uint4 qa = *(const uint4*)&g_Q[rA];
        uint4 qb = *(const uint4*)&g_Q[rA + NTOK];
        uint4 ka = *(const uint4*)&g_K[rA];
        uint4 kb = *(const uint4*)&g_K[rA + NTOK];
        const uint32_t qaw[4] = {qa.x, qa.y, qa.z, qa.w};
        const uint32_t qbw[4] = {qb.x, qb.y, qb.z, qb.w};
        const uint32_t kaw[4] = {ka.x, ka.y, ka.z, ka.w};
        const uint32_t kbw[4] = {kb.x, kb.y, kb.z, kb.w};
        const int off = w * QK_STR + (2 * s) * 2;
#pragma unroll
        for (int j = 0; j < 4; j++) {
            uint32_t qe = __byte_perm(qaw[j], qbw[j], 0x5410);
            uint32_t qo = __byte_perm(qaw[j], qbw[j], 0x7632);
            uint32_t ke = __byte_perm(kaw[j], kbw[j], 0x5410);
            uint32_t ko = __byte_perm(kaw[j], kbw[j], 0x7632);
            *(uint32_t*)(grp + (2 * j)     * QK_TOK + off) = qe;
            *(uint32_t*)(grp + (2 * j + 1) * QK_TOK + off) = qo;
            *(uint32_t*)(grp + GOFF_K + (2 * j)     * QK_TOK + off) = ke;
            *(uint32_t*)(grp + GOFF_K + (2 * j + 1) * QK_TOK + off) = ko;
        }

        // V: rows (h2*64 + dv, +32); h2 = w>>1, dv = (w&1)*16 + s
        const int h2 = w >> 1;
        const int dv = ((w & 1) << 4) | s;
        const size_t rV = base + (size_t)(h2 * 64 + dv) * NTOK + hh * 8;
        uint4 va = *(const uint4*)&g_V[rV];
        uint4 vb = *(const uint4*)&g_V[rV + (size_t)32 * NTOK];
        const uint32_t vaw[4] = {va.x, va.y, va.z, va.w};
        const uint32_t vbw[4] = {vb.x, vb.y, vb.z, vb.w};
        const int voff = dv * VT_STR + h2 * 4;
#pragma unroll
        for (int j = 0; j < 4; j++) {
            uint32_t ve = __byte_perm(vaw[j], vbw[j], 0x5410);
            uint32_t vo = __byte_perm(vaw[j], vbw[j], 0x7632);
            *(uint32_t*)(grp + GOFF_V + (2 * j)     * VT_TOK + voff) = ve;
            *(uint32_t*)(grp + GOFF_V + (2 * j + 1) * VT_TOK + voff) = vo;
        }

        // Ksum (512 threads, one element each), padded rows of 36 floats
        Ksm[(tid >> 5) * 36 + (tid & 31)] = g_Ksum[b * CH + tid];
    }
    __syncthreads();

    // ---- MMA phase: warp w = token w; group g = w>>3, slot = w&7 ----
    const int g    = w >> 3;
    const int slot = w & 7;
    const int row  = l & 15;
    const int half = l >> 4;
    const int gr   = l >> 2, kc = l & 3;

    const uint32_t gb  = sb + g * GRP;
    const uint32_t qb_ = gb + slot * QK_TOK;
    const uint32_t kb_ = gb + GOFF_K + slot * QK_TOK;
    const uint32_t vb_ = gb + GOFF_V + slot * VT_TOK;

    uint32_t aQ0[4], aQ1[4], kf0[4], kf1[4];
    ldsm_x4(aQ0, qb_ + row * QK_STR + half * 16);
    ldsm_x4(aQ1, qb_ + row * QK_STR + 32 + half * 16);
    ldsm_x4(kf0, kb_ + row * QK_STR + half * 16);
    ldsm_x4(kf1, kb_ + row * QK_STR + 32 + half * 16);

    float S0[4] = {0.f, 0.f, 0.f, 0.f};
    float S1[4] = {0.f, 0.f, 0.f, 0.f};
    {
        uint32_t bb[2];
        bb[0] = kf0[0]; bb[1] = kf0[2]; mma_bf16(S0, aQ0, bb);
        bb[0] = kf0[1]; bb[1] = kf0[3]; mma_bf16(S1, aQ0, bb);
        bb[0] = kf1[0]; bb[1] = kf1[2]; mma_bf16(S0, aQ1, bb);
        bb[0] = kf1[1]; bb[1] = kf1[3]; mma_bf16(S1, aQ1, bb);
    }

    // Z: lanes 0..15, h = lane  (last reads of the Q region)
    if (l < 16) {
        unsigned long long acc = 0;
        const int h = l;
#pragma unroll
        for (int d2 = 0; d2 < 16; d2++) {
            uint32_t qp;
            asm volatile("ld.shared.b32 %0, [%1];" : "=r"(qp)
                         : "r"(qb_ + h * QK_STR + d2 * 4));
            unsigned long long kq = *(const unsigned long long*)(Ksm + h * 36 + 2 * d2);
            fma2(acc, bfpair_f32x2(qp), kq);
        }
        float x, y;
        asm("mov.b64 {%0, %1}, %2;" : "=f"(x), "=f"(y) : "l"(acc));
        Zs[w * 17 + h] = 1.f / (x + y + 1e-5f);
    }

    // S -> A2 fragments (accumulator layout == A-operand layout)
    uint32_t a2[4];
    a2[0] = packbf(S0[0], S0[1]);
    a2[1] = packbf(S0[2], S0[3]);
    a2[2] = packbf(S1[0], S1[1]);
    a2[3] = packbf(S1[2], S1[3]);

    uint32_t vf0[4], vf1[4];
    ldsm_x4(vf0, vb_ + row * VT_STR + half * 16);
    ldsm_x4(vf1, vb_ + (16 + row) * VT_STR + half * 16);

    float O[4][4];
#pragma unroll
    for (int gg = 0; gg < 4; gg++)
#pragma unroll
        for (int r = 0; r < 4; r++) O[gg][r] = 0.f;
    {
        uint32_t bb[2];
        bb[0] = vf0[0]; bb[1] = vf0[2]; mma_bf16(O[0], a2, bb);
        bb[0] = vf0[1]; bb[1] = vf0[3]; mma_bf16(O[1], a2, bb);
        bb[0] = vf1[0]; bb[1] = vf1[2]; mma_bf16(O[2], a2, bb);
        bb[0] = vf1[1]; bb[1] = vf1[3]; mma_bf16(O[3], a2, bb);
    }

    // barrier: all Q reads (ldsm + Z loop, all warps) complete before O
    // staging overwrites the Q region
    __syncthreads();

    const float zlo = Zs[w * 17 + gr];
    const float zhi = Zs[w * 17 + gr + 8];
#pragma unroll
    for (int gg = 0; gg < 4; gg++) {
        const int c2a = gr * 16 + gg * 4 + kc;
        const int c2b = (gr + 8) * 16 + gg * 4 + kc;
        uint32_t wlo = packbf(O[gg][0] * zlo, O[gg][1] * zlo);
        uint32_t whi = packbf(O[gg][2] * zhi, O[gg][3] * zhi);
        *(uint32_t*)(smraw + g * GRP + GOFF_O + (sigma_o(c2a) * 9 + slot) * 4) = wlo;
        *(uint32_t*)(smraw + g * GRP + GOFF_O + (sigma_o(c2b) * 9 + slot) * 4) = whi;
    }
    __syncthreads();

    // ---- store phase (coalesced): lane pair = one c2-row, two token halves ----
    {
        const int s2 = l >> 1;               // 0..15
        const int tg = l & 1;                // token group
        const int c2 = w * 16 + s2;          // 0..255
        const uint32_t ob = (uint32_t)(tg * GRP + GOFF_O) +
                            (uint32_t)(sigma_o(c2) * 9) * 4;
        uint32_t ww[8];
#pragma unroll
        for (int tt = 0; tt < 8; tt++)
            ww[tt] = *(const uint32_t*)(smraw + ob + tt * 4);
        uint4 lo, hi;
        lo.x = __byte_perm(ww[0], ww[1], 0x5410);
        lo.y = __byte_perm(ww[2], ww[3], 0x5410);
        lo.z = __byte_perm(ww[4], ww[5], 0x5410);
        lo.w = __byte_perm(ww[6], ww[7], 0x5410);
        hi.x = __byte_perm(ww[0], ww[1], 0x7632);
        hi.y = __byte_perm(ww[2], ww[3], 0x7632);
        hi.z = __byte_perm(ww[4], ww[5], 0x7632);
        hi.w = __byte_perm(ww[6], ww[7], 0x7632);
        const size_t rM = base + (size_t)(2 * c2) * NTOK + tg * 8;
        *(uint4*)&g_M[rM]        = lo;
        *(uint4*)&g_M[rM + NTOK] = hi;
    }
}

// =====================================================================
extern "C" void kernel_launch(void* const* d_in, const int* in_sizes, int n_in,
                              void* d_out, int out_size)
{
    (void)in_sizes; (void)n_in; (void)out_size;
    const float* q  = (const float*)d_in[0];
    const float* k  = (const float*)d_in[1];
    const float* v  = (const float*)d_in[2];
    const float* Wq = (const float*)d_in[3];
    const float* Wk = (const float*)d_in[4];
    const float* Wv = (const float*)d_in[5];
    const float* Wp = (const float*)d_in[6];
    const float* bp = (const float*)d_in[7];
    float* out = (float*)d_out;

    void *wt, *x, *Qp, *Kp, *Vp, *Mp;
    cudaGetSymbolAddress(&wt, g_Wt);
    cudaGetSymbolAddress(&x,  g_X);
    cudaGetSymbolAddress(&Qp, g_Q);
    cudaGetSymbolAddress(&Kp, g_K);
    cudaGetSymbolAddress(&Vp, g_V);
    cudaGetSymbolAddress(&Mp, g_M);
    __nv_bfloat16* Wt = (__nv_bfloat16*)wt;
    __nv_bfloat16* X  = (__nv_bfloat16*)x;
    const size_t XS = (size_t)BATCH * CH * NTOK;

    cudaFuncSetAttribute(gemm_ca<true,  __nv_bfloat16, false>,
                         cudaFuncAttributeMaxDynamicSharedMemorySize, GEMM_SMEM);
    cudaFuncSetAttribute(gemm_ca<false, float, true>,
                         cudaFuncAttributeMaxDynamicSharedMemorySize, GEMM_SMEM);
    cudaFuncSetAttribute(mid_kernel,
                         cudaFuncAttributeMaxDynamicSharedMemorySize, MID_SMEM);

    // 1. prep (wprep also zeroes g_Ksum)
    wprep<<<dim3(16, 16, 4), 256>>>(Wq, Wk, Wv, Wp, Wt);
    xconv<<<dim3(8192, 1, 3), 256>>>((const float4*)q, (const float4*)k,
                                     (const float4*)v, (uint4*)X);

    // 2. projections (fused 3-in-1; K-proj accumulates Ksum via atomics)
    dim3 gp(NTOK / 128, CH / 128, 3 * BATCH);
    gemm_ca<true, __nv_bfloat16, false><<<gp, 256, GEMM_SMEM>>>(
        Wt, Wt + CH * CH, Wt + 2 * CH * CH,
        X, X + XS, X + 2 * XS,
        Qp, Kp, Vp, nullptr);

    // 3. middle (tensor-core, 16 tokens/block, 3 CTAs/SM)
    mid_kernel<<<BATCH * (NTOK / 16), 512, MID_SMEM>>>();

    // 4. output projection
    dim3 gf(NTOK / 128, CH / 128, BATCH);
    gemm_ca<false, float, true><<<gf, 256, GEMM_SMEM>>>(
        Wt + 3 * CH * CH, nullptr, nullptr,
        (__nv_bfloat16*)Mp, nullptr, nullptr,
        out, nullptr, nullptr, bp);
}

// round 14
// speedup vs baseline: 1.0385x; 1.0385x over previous
#include <cuda_runtime.h>
#include <cuda_bf16.h>
#include <cstdint>
#include <cmath>

#define BATCH 8
#define CH    512
#define NTOK  4096

// ---------------- scratch (device globals) ----------------
__device__ __nv_bfloat16 g_Wt[4 * CH * CH];           // transposed bf16 weights [c][d]
__device__ __nv_bfloat16 g_X [3 * BATCH * CH * NTOK]; // bf16 q,k,v in [b][c][n]
__device__ __nv_bfloat16 g_Q [BATCH * CH * NTOK];
__device__ __nv_bfloat16 g_K [BATCH * CH * NTOK];
__device__ __nv_bfloat16 g_V [BATCH * CH * NTOK];
__device__ __nv_bfloat16 g_M [BATCH * CH * NTOK];
__device__ float g_Ksum[BATCH * CH];

// ---------------- helpers ----------------
__device__ __forceinline__ uint32_t smem_u32(const void* p) {
    uint32_t a;
    asm("{ .reg .u64 t; cvta.to.shared.u64 t, %1; cvt.u32.u64 %0, t; }" : "=r"(a) : "l"(p));
    return a;
}
__device__ __forceinline__ uint32_t bf2u(__nv_bfloat162 h) {
    union { __nv_bfloat162 h; uint32_t u; } z; z.h = h; return z.u;
}
__device__ __forceinline__ void mma_bf16(float c[4], const uint32_t a[4], const uint32_t b[2]) {
    asm volatile(
        "mma.sync.aligned.m16n8k16.row.col.f32.bf16.bf16.f32 "
        "{%0,%1,%2,%3}, {%4,%5,%6,%7}, {%8,%9}, {%0,%1,%2,%3};"
        : "+f"(c[0]), "+f"(c[1]), "+f"(c[2]), "+f"(c[3])
        : "r"(a[0]), "r"(a[1]), "r"(a[2]), "r"(a[3]), "r"(b[0]), "r"(b[1]));
}
__device__ __forceinline__ void ldsm_x4(uint32_t r[4], uint32_t addr) {
    asm volatile("ldmatrix.sync.aligned.m8n8.x4.shared.b16 {%0,%1,%2,%3}, [%4];"
                 : "=r"(r[0]), "=r"(r[1]), "=r"(r[2]), "=r"(r[3]) : "r"(addr));
}
__device__ __forceinline__ void ldsm_x4_t(uint32_t r[4], uint32_t addr) {
    asm volatile("ldmatrix.sync.aligned.m8n8.x4.trans.shared.b16 {%0,%1,%2,%3}, [%4];"
                 : "=r"(r[0]), "=r"(r[1]), "=r"(r[2]), "=r"(r[3]) : "r"(addr));
}
#define CP16(dst, src) \
    asm volatile("cp.async.cg.shared.global [%0], [%1], 16;" :: "r"(dst), "l"(src) : "memory")
#define CP_COMMIT() asm volatile("cp.async.commit_group;" ::: "memory")
#define CP_WAIT(n)  asm volatile("cp.async.wait_group %0;" :: "n"(n) : "memory")

// packed f32x2 ops (sm_100+ base PTX)
__device__ __forceinline__ void fma2(unsigned long long& acc,
                                     unsigned long long a, unsigned long long b) {
    asm("fma.rn.f32x2 %0, %1, %2, %0;" : "+l"(acc) : "l"(a), "l"(b));
}
__device__ __forceinline__ unsigned long long bfpair_f32x2(uint32_t v) {
    union { uint32_t u; __nv_bfloat162 h; } z; z.u = v;
    float2 f = __bfloat1622float2(z.h);
    unsigned long long r;
    asm("mov.b64 %0, {%1, %2};" : "=l"(r) : "f"(f.x), "f"(f.y));
    return r;
}
// pack two f32 -> bf16x2 (lo = a, hi = b)
__device__ __forceinline__ uint32_t packbf(float a, float b) {
    uint32_t r;
    asm("cvt.rn.bf16x2.f32 %0, %1, %2;" : "=r"(r) : "f"(b), "f"(a));
    return r;
}

// =====================================================================
// weight prep: W fp32 [d][c] -> bf16 [c][d]  (grid 16,16,4); also zeros g_Ksum
// =====================================================================
__global__ __launch_bounds__(256) void wprep(
    const float* __restrict__ W0, const float* __restrict__ W1,
    const float* __restrict__ W2, const float* __restrict__ W3,
    __nv_bfloat16* __restrict__ D)
{
    __shared__ float t[32][33];
    if (blockIdx.z == 0 && blockIdx.y == 0)
        g_Ksum[blockIdx.x * 256 + threadIdx.x] = 0.f;
    const int z = blockIdx.z;
    const float* S = (z == 0) ? W0 : (z == 1) ? W1 : (z == 2) ? W2 : W3;
    __nv_bfloat16* Dz = D + (size_t)z * CH * CH;
    const int d0 = blockIdx.x * 32, c0 = blockIdx.y * 32;
    const int x = threadIdx.x & 31, y = threadIdx.x >> 5;
#pragma unroll
    for (int i = 0; i < 4; i++)
        t[y + 8 * i][x] = S[(size_t)(d0 + y + 8 * i) * CH + c0 + x];
    __syncthreads();
    const int m2 = threadIdx.x & 15, r0 = threadIdx.x >> 4;
#pragma unroll
    for (int i = 0; i < 2; i++) {
        const int r = r0 + 16 * i;
        __nv_bfloat162 h = __float22bfloat162_rn(make_float2(t[m2 * 2][r], t[m2 * 2 + 1][r]));
        *(__nv_bfloat162*)&Dz[(size_t)(c0 + r) * CH + d0 + m2 * 2] = h;
    }
}

// =====================================================================
// input prep: fp32 -> bf16 elementwise (grid 8192,1,3)
// =====================================================================
__global__ __launch_bounds__(256) void xconv(
    const float4* __restrict__ s0, const float4* __restrict__ s1,
    const float4* __restrict__ s2, uint4* __restrict__ d)
{
    const int z = blockIdx.z;
    const float4* s = (z == 0) ? s0 : (z == 1) ? s1 : s2;
    uint4* dz = d + (size_t)z * (BATCH * CH * NTOK / 8);
    const size_t i = (size_t)blockIdx.x * 256 + threadIdx.x;
    float4 a = s[2 * i], b = s[2 * i + 1];
    uint4 o;
    o.x = bf2u(__float22bfloat162_rn(make_float2(a.x, a.y)));
    o.y = bf2u(__float22bfloat162_rn(make_float2(a.z, a.w)));
    o.z = bf2u(__float22bfloat162_rn(make_float2(b.x, b.y)));
    o.w = bf2u(__float22bfloat162_rn(make_float2(b.z, b.w)));
    dz[i] = o;
}

// =====================================================================
// GEMM: C[b,d,n] = sum_c At[c,d] * B[b,c,n]  (+elu+1 | +bias | +ksum atomics)
// BM=BN=128, BK=32, 4-stage cp.async, 256 thr, 8 warps (4m x 2n), 32x64.
// (unchanged from validated baseline)
// =====================================================================
#define STG_SZ 16384
#define GEMM_SMEM (4 * STG_SZ)

template<bool PROJ, typename OutT, bool BIAS>
__global__ __launch_bounds__(256, 2) void gemm_ca(
    const __nv_bfloat16* __restrict__ A0, const __nv_bfloat16* __restrict__ A1,
    const __nv_bfloat16* __restrict__ A2,
    const __nv_bfloat16* __restrict__ X0, const __nv_bfloat16* __restrict__ X1,
    const __nv_bfloat16* __restrict__ X2,
    void* C0, void* C1, void* C2, const float* __restrict__ bias)
{
    extern __shared__ char smem[];
    const uint32_t sb = smem_u32(smem);

    int b; bool elu; int which = 0;
    const __nv_bfloat16 *A, *B; OutT* C;
    if (PROJ) {
        which = blockIdx.z >> 3; b = blockIdx.z & 7;
        A = (which == 0) ? A0 : (which == 1) ? A1 : A2;
        B = (which == 0) ? X0 : (which == 1) ? X1 : X2;
        C = (OutT*)((which == 0) ? C0 : (which == 1) ? C1 : C2);
        elu = (which < 2);
    } else {
        b = blockIdx.z; A = A0; B = X0; C = (OutT*)C0; elu = false;
    }

    const int m0 = blockIdx.y * 128, n0 = blockIdx.x * 128;
    const __nv_bfloat16* Bb = B + (size_t)b * CH * NTOK;
    OutT* Cb = C + (size_t)b * CH * NTOK;

    const int tid = threadIdx.x;
    const int lane = tid & 31, wid = tid >> 5;
    const int wm = wid & 3, wn = wid >> 2;
    const int gr = lane >> 2, kc = lane & 3;

    const int lr = tid >> 3;
    const int lc = (tid & 7) * 2;
    const int swz = lr & 7;

    const int klow = ((lane >> 3) & 1) * 8 + (lane & 7);
    const int cg   = lane >> 4;

    float acc[2][8][4];
#pragma unroll
    for (int i = 0; i < 2; i++)
#pragma unroll
        for (int j = 0; j < 8; j++)
#pragma unroll
            for (int r = 0; r < 4; r++) acc[i][j][r] = 0.f;

    auto issue = [&](int kt, int s) {
        const __nv_bfloat16* pa = A  + (size_t)(kt * 32 + lr) * CH   + m0 + lc * 8;
        const __nv_bfloat16* pb = Bb + (size_t)(kt * 32 + lr) * NTOK + n0 + lc * 8;
        const uint32_t base = sb + s * STG_SZ + lr * 256;
        CP16(base + ((lc     ^ swz) * 16),        pa);
        CP16(base + (((lc+1) ^ swz) * 16),        pa + 8);
        CP16(base + ((lc     ^ swz) * 16) + 8192, pb);
        CP16(base + (((lc+1) ^ swz) * 16) + 8192, pb + 8);
    };

#pragma unroll
    for (int s = 0; s < 3; s++) { issue(s, s); CP_COMMIT(); }

    const int KT = CH / 32;  // 16
#pragma unroll 1
    for (int kt = 0; kt < KT; ++kt) {
        CP_WAIT(2);
        __syncthreads();
        const int s = kt & 3;
        const uint32_t stA = sb + s * STG_SZ;

#pragma unroll
        for (int ks = 0; ks < 2; ++ks) {
            const int krow = ks * 16 + klow;
            const int kx = krow & 7;
            const uint32_t rb = stA + krow * 256;

            uint32_t af[2][4];
#pragma unroll
            for (int i = 0; i < 2; i++) {
                const int mc = wm * 4 + i * 2 + cg;
                uint32_t r[4];
                ldsm_x4_t(r, rb + ((mc ^ kx) * 16));
                af[i][0] = r[0]; af[i][1] = r[2]; af[i][2] = r[1]; af[i][3] = r[3];
            }
            uint32_t bf[8][2];
#pragma unroll
            for (int jj = 0; jj < 4; jj++) {
                const int nc = wn * 8 + jj * 2 + cg;
                uint32_t r[4];
                ldsm_x4_t(r, rb + 8192 + ((nc ^ kx) * 16));
                bf[jj * 2][0]     = r[0];
                bf[jj * 2][1]     = r[1];
                bf[jj * 2 + 1][0] = r[2];
                bf[jj * 2 + 1][1] = r[3];
            }
#pragma unroll
            for (int i = 0; i < 2; i++)
#pragma unroll
                for (int j = 0; j < 8; j++)
                    mma_bf16(acc[i][j], af[i], bf[j]);
        }

        if (kt + 3 < KT) issue(kt + 3, (kt + 3) & 3);
        CP_COMMIT();
    }

    // epilogue (+ fused Ksum for which==1)
#pragma unroll
    for (int i = 0; i < 2; i++) {
        const int row = m0 + wm * 32 + i * 16 + gr;
        const float bi0 = BIAS ? bias[row] : 0.f;
        const float bi1 = BIAS ? bias[row + 8] : 0.f;
        float rs0 = 0.f, rs1 = 0.f;
#pragma unroll
        for (int j = 0; j < 8; j++) {
            const int col = n0 + wn * 64 + j * 8 + kc * 2;
            float c0 = acc[i][j][0], c1 = acc[i][j][1];
            float c2 = acc[i][j][2], c3 = acc[i][j][3];
            if (PROJ && elu) {
                c0 = (c0 > 0.f) ? (c0 + 1.f) : __expf(c0);
                c1 = (c1 > 0.f) ? (c1 + 1.f) : __expf(c1);
                c2 = (c2 > 0.f) ? (c2 + 1.f) : __expf(c2);
                c3 = (c3 > 0.f) ? (c3 + 1.f) : __expf(c3);
            }
            if (BIAS) { c0 += bi0; c1 += bi0; c2 += bi1; c3 += bi1; }
            if (PROJ && which == 1) { rs0 += c0 + c1; rs1 += c2 + c3; }
            if constexpr (sizeof(OutT) == 2) {
                *(__nv_bfloat162*)&Cb[(size_t)row * NTOK + col] =
                    __float22bfloat162_rn(make_float2(c0, c1));
                *(__nv_bfloat162*)&Cb[(size_t)(row + 8) * NTOK + col] =
                    __float22bfloat162_rn(make_float2(c2, c3));
            } else {
                *(float2*)&Cb[(size_t)row * NTOK + col]       = make_float2(c0, c1);
                *(float2*)&Cb[(size_t)(row + 8) * NTOK + col] = make_float2(c2, c3);
            }
        }
        if (PROJ && which == 1) {
            rs0 += __shfl_xor_sync(0xffffffffu, rs0, 1);
            rs0 += __shfl_xor_sync(0xffffffffu, rs0, 2);
            rs1 += __shfl_xor_sync(0xffffffffu, rs1, 1);
            rs1 += __shfl_xor_sync(0xffffffffu, rs1, 2);
            if (kc == 0) {
                atomicAdd(&g_Ksum[b * CH + row],     rs0);
                atomicAdd(&g_Ksum[b * CH + row + 8], rs1);
            }
        }
    }
}

// =====================================================================
// Middle stage, tensor-core edition v5: 32 tokens/block, 1024 threads.
// Four 8-token groups (hh=0..3); per-group layouts identical to the
// validated v3 design; round-12 barrier structure (no Q/O overlay).
// Gmem rows are 64B (lane-quads) -> nL=8 lines/LDG and /STG.
// GRP=32800 (== 8 words mod 32): Q/K STS bank = s + 8*hh, conflict-free.
// O arena separate, stride 9248 (== 8 words): store-phase LDS <= 2-way.
// smem 168.6KB -> 1 CTA/SM (32 warps).
// =====================================================================
#define QK_STR 80
#define QK_TOK 1280
#define VT_STR 48
#define VT_TOK 1536
#define GRP5   32800          // Q(10240)+K(10240)+V(12288) + 32B pad
#define GOFF_K 10240
#define GOFF_V 20480
#define OARENA (4 * GRP5)                 // 131200 (== 0 mod 128)
#define OSTR   9248                       // 9216 + 32B pad (== 8 words mod 32)
#define OFF_Z  (OARENA + 4 * OSTR)        // 168192; 32 tokens * 17 floats
#define OFF_KS (OFF_Z + 32 * 17 * 4)      // 170368; 16 * 36 floats
#define MID_SMEM (OFF_KS + 16 * 36 * 4)   // 172672

__device__ __forceinline__ int sigma_o(int c2) {
    return (c2 & 3) | (((c2 >> 4) & 7) << 2) | (((c2 >> 2) & 3) << 5) | (((c2 >> 7) & 1) << 7);
}

__global__ __launch_bounds__(1024) void mid_kernel()
{
    extern __shared__ char smraw[];
    const uint32_t sb = smem_u32(smraw);
    float* Zs  = (float*)(smraw + OFF_Z);
    float* Ksm = (float*)(smraw + OFF_KS);

    const int blk = blockIdx.x;              // BATCH * 128
    const int b   = blk >> 7;
    const int n0  = (blk & 127) * 32;
    const size_t base = (size_t)b * CH * NTOK + n0;
    const int tid = threadIdx.x;
    const int l   = tid & 31;
    const int w   = tid >> 5;                // 0..31

    // ---- load phase ----
    {
        const int s  = l >> 2;               // 0..7
        const int hh = l & 3;                // token group (tokens hh*8 .. hh*8+7)
        char* grp = smraw + hh * GRP5;

        // Q, K: thread owns c2 = w*8 + s (c rows 2*c2, 2*c2+1)
        const int c2 = w * 8 + s;
        const size_t rA = base + (size_t)(2 * c2) * NTOK + hh * 8;
        uint4 qa = *(const uint4*)&g_Q[rA];
        uint4 qb = *(const uint4*)&g_Q[rA + NTOK];
        uint4 ka = *(const uint4*)&g_K[rA];
        uint4 kb = *(const uint4*)&g_K[rA + NTOK];
        const uint32_t qaw[4] = {qa.x, qa.y, qa.z, qa.w};
        const uint32_t qbw[4] = {qb.x, qb.y, qb.z, qb.w};
        const uint32_t kaw[4] = {ka.x, ka.y, ka.z, ka.w};
        const uint32_t kbw[4] = {kb.x, kb.y, kb.z, kb.w};
        const int hq  = c2 >> 4;
        const int d2m = c2 & 15;
        const int off = hq * QK_STR + d2m * 4;
#pragma unroll
        for (int j = 0; j < 4; j++) {
            uint32_t qe = __byte_perm(qaw[j], qbw[j], 0x5410);
            uint32_t qo = __byte_perm(qaw[j], qbw[j], 0x7632);
            uint32_t ke = __byte_perm(kaw[j], kbw[j], 0x5410);
            uint32_t ko = __byte_perm(kaw[j], kbw[j], 0x7632);
            *(uint32_t*)(grp + (2 * j)     * QK_TOK + off) = qe;
            *(uint32_t*)(grp + (2 * j + 1) * QK_TOK + off) = qo;
            *(uint32_t*)(grp + GOFF_K + (2 * j)     * QK_TOK + off) = ke;
            *(uint32_t*)(grp + GOFF_K + (2 * j + 1) * QK_TOK + off) = ko;
        }

        // V: rows (h2*64 + dv, +32); h2 = w>>2, dv = (w&3)*8 + s
        const int h2 = w >> 2;
        const int dv = ((w & 3) << 3) | s;
        const size_t rV = base + (size_t)(h2 * 64 + dv) * NTOK + hh * 8;
        uint4 va = *(const uint4*)&g_V[rV];
        uint4 vb = *(const uint4*)&g_V[rV + (size_t)32 * NTOK];
        const uint32_t vaw[4] = {va.x, va.y, va.z, va.w};
        const uint32_t vbw[4] = {vb.x, vb.y, vb.z, vb.w};
        const int voff = dv * VT_STR + h2 * 4;
#pragma unroll
        for (int j = 0; j < 4; j++) {
            uint32_t ve = __byte_perm(vaw[j], vbw[j], 0x5410);
            uint32_t vo = __byte_perm(vaw[j], vbw[j], 0x7632);
            *(uint32_t*)(grp + GOFF_V + (2 * j)     * VT_TOK + voff) = ve;
            *(uint32_t*)(grp + GOFF_V + (2 * j + 1) * VT_TOK + voff) = vo;
        }

        // Ksum, padded rows of 36 floats (first 512 threads)
        if (tid < CH)
            Ksm[(tid >> 5) * 36 + (tid & 31)] = g_Ksum[b * CH + tid];
    }
    __syncthreads();

    // ---- MMA phase: warp w = token w; group g = w>>3, slot = w&7 ----
    const int g    = w >> 3;
    const int slot = w & 7;
    const int row  = l & 15;
    const int half = l >> 4;
    const int gr   = l >> 2, kc = l & 3;

    const uint32_t gb  = sb + g * GRP5;
    const uint32_t qb_ = gb + slot * QK_TOK;
    const uint32_t kb_ = gb + GOFF_K + slot * QK_TOK;
    const uint32_t vb_ = gb + GOFF_V + slot * VT_TOK;

    uint32_t aQ0[4], aQ1[4], kf0[4], kf1[4];
    ldsm_x4(aQ0, qb_ + row * QK_STR + half * 16);
    ldsm_x4(aQ1, qb_ + row * QK_STR + 32 + half * 16);
    ldsm_x4(kf0, kb_ + row * QK_STR + half * 16);
    ldsm_x4(kf1, kb_ + row * QK_STR + 32 + half * 16);

    float S0[4] = {0.f, 0.f, 0.f, 0.f};
    float S1[4] = {0.f, 0.f, 0.f, 0.f};
    {
        uint32_t bb[2];
        bb[0] = kf0[0]; bb[1] = kf0[2]; mma_bf16(S0, aQ0, bb);
        bb[0] = kf0[1]; bb[1] = kf0[3]; mma_bf16(S1, aQ0, bb);
        bb[0] = kf1[0]; bb[1] = kf1[2]; mma_bf16(S0, aQ1, bb);
        bb[0] = kf1[1]; bb[1] = kf1[3]; mma_bf16(S1, aQ1, bb);
    }

    // Z: lanes 0..15, h = lane
    if (l < 16) {
        unsigned long long acc = 0;
        const int h = l;
#pragma unroll
        for (int d2 = 0; d2 < 16; d2++) {
            uint32_t qp;
            asm volatile("ld.shared.b32 %0, [%1];" : "=r"(qp)
                         : "r"(qb_ + h * QK_STR + d2 * 4));
            unsigned long long kq = *(const unsigned long long*)(Ksm + h * 36 + 2 * d2);
            fma2(acc, bfpair_f32x2(qp), kq);
        }
        float x, y;
        asm("mov.b64 {%0, %1}, %2;" : "=f"(x), "=f"(y) : "l"(acc));
        Zs[w * 17 + h] = 1.f / (x + y + 1e-5f);
    }

    // S -> A2 fragments (accumulator layout == A-operand layout)
    uint32_t a2[4];
    a2[0] = packbf(S0[0], S0[1]);
    a2[1] = packbf(S0[2], S0[3]);
    a2[2] = packbf(S1[0], S1[1]);
    a2[3] = packbf(S1[2], S1[3]);

    uint32_t vf0[4], vf1[4];
    ldsm_x4(vf0, vb_ + row * VT_STR + half * 16);
    ldsm_x4(vf1, vb_ + (16 + row) * VT_STR + half * 16);

    float O[4][4];
#pragma unroll
    for (int gg = 0; gg < 4; gg++)
#pragma unroll
        for (int r = 0; r < 4; r++) O[gg][r] = 0.f;
    {
        uint32_t bb[2];
        bb[0] = vf0[0]; bb[1] = vf0[2]; mma_bf16(O[0], a2, bb);
        bb[0] = vf0[1]; bb[1] = vf0[3]; mma_bf16(O[1], a2, bb);
        bb[0] = vf1[0]; bb[1] = vf1[2]; mma_bf16(O[2], a2, bb);
        bb[0] = vf1[1]; bb[1] = vf1[3]; mma_bf16(O[3], a2, bb);
    }

    __syncwarp();
    const float zlo = Zs[w * 17 + gr];
    const float zhi = Zs[w * 17 + gr + 8];
#pragma unroll
    for (int gg = 0; gg < 4; gg++) {
        const int c2a = gr * 16 + gg * 4 + kc;
        const int c2b = (gr + 8) * 16 + gg * 4 + kc;
        uint32_t wlo = packbf(O[gg][0] * zlo, O[gg][1] * zlo);
        uint32_t whi = packbf(O[gg][2] * zhi, O[gg][3] * zhi);
        *(uint32_t*)(smraw + OARENA + g * OSTR + (sigma_o(c2a) * 9 + slot) * 4) = wlo;
        *(uint32_t*)(smraw + OARENA + g * OSTR + (sigma_o(c2b) * 9 + slot) * 4) = whi;
    }
    __syncthreads();

    // ---- store phase: lane quad = one c2-row, four token groups of 8 ----
    {
        const int s2 = l >> 2;               // 0..7
        const int tg = l & 3;                // token group
        const int c2 = w * 8 + s2;           // 0..255
        const uint32_t ob = (uint32_t)(OARENA + tg * OSTR) +
                            (uint32_t)(sigma_o(c2) * 9) * 4;
        uint32_t ww[8];
#pragma unroll
        for (int tt = 0; tt < 8; tt++)
            ww[tt] = *(const uint32_t*)(smraw + ob + tt * 4);
        uint4 lo, hi;
        lo.x = __byte_perm(ww[0], ww[1], 0x5410);
        lo.y = __byte_perm(ww[2], ww[3], 0x5410);
        lo.z = __byte_perm(ww[4], ww[5], 0x5410);
        lo.w = __byte_perm(ww[6], ww[7], 0x5410);
        hi.x = __byte_perm(ww[0], ww[1], 0x7632);
        hi.y = __byte_perm(ww[2], ww[3], 0x7632);
        hi.z = __byte_perm(ww[4], ww[5], 0x7632);
        hi.w = __byte_perm(ww[6], ww[7], 0x7632);
        const size_t rM = base + (size_t)(2 * c2) * NTOK + tg * 8;
        *(uint4*)&g_M[rM]        = lo;
        *(uint4*)&g_M[rM + NTOK] = hi;
    }
}

// =====================================================================
extern "C" void kernel_launch(void* const* d_in, const int* in_sizes, int n_in,
                              void* d_out, int out_size)
{
    (void)in_sizes; (void)n_in; (void)out_size;
    const float* q  = (const float*)d_in[0];
    const float* k  = (const float*)d_in[1];
    const float* v  = (const float*)d_in[2];
    const float* Wq = (const float*)d_in[3];
    const float* Wk = (const float*)d_in[4];
    const float* Wv = (const float*)d_in[5];
    const float* Wp = (const float*)d_in[6];
    const float* bp = (const float*)d_in[7];
    float* out = (float*)d_out;

    void *wt, *x, *Qp, *Kp, *Vp, *Mp;
    cudaGetSymbolAddress(&wt, g_Wt);
    cudaGetSymbolAddress(&x,  g_X);
    cudaGetSymbolAddress(&Qp, g_Q);
    cudaGetSymbolAddress(&Kp, g_K);
    cudaGetSymbolAddress(&Vp, g_V);
    cudaGetSymbolAddress(&Mp, g_M);
    __nv_bfloat16* Wt = (__nv_bfloat16*)wt;
    __nv_bfloat16* X  = (__nv_bfloat16*)x;
    const size_t XS = (size_t)BATCH * CH * NTOK;

    cudaFuncSetAttribute(gemm_ca<true,  __nv_bfloat16, false>,
                         cudaFuncAttributeMaxDynamicSharedMemorySize, GEMM_SMEM);
    cudaFuncSetAttribute(gemm_ca<false, float, true>,
                         cudaFuncAttributeMaxDynamicSharedMemorySize, GEMM_SMEM);
    cudaFuncSetAttribute(mid_kernel,
                         cudaFuncAttributeMaxDynamicSharedMemorySize, MID_SMEM);

    // 1. prep (wprep also zeroes g_Ksum)
    wprep<<<dim3(16, 16, 4), 256>>>(Wq, Wk, Wv, Wp, Wt);
    xconv<<<dim3(8192, 1, 3), 256>>>((const float4*)q, (const float4*)k,
                                     (const float4*)v, (uint4*)X);

    // 2. projections (fused 3-in-1; K-proj accumulates Ksum via atomics)
    dim3 gp(NTOK / 128, CH / 128, 3 * BATCH);
    gemm_ca<true, __nv_bfloat16, false><<<gp, 256, GEMM_SMEM>>>(
        Wt, Wt + CH * CH, Wt + 2 * CH * CH,
        X, X + XS, X + 2 * XS,
        Qp, Kp, Vp, nullptr);

    // 3. middle (tensor-core, 32 tokens/block)
    mid_kernel<<<BATCH * (NTOK / 32), 1024, MID_SMEM>>>();

    // 4. output projection
    dim3 gf(NTOK / 128, CH / 128, BATCH);
    gemm_ca<false, float, true><<<gf, 256, GEMM_SMEM>>>(
        Wt + 3 * CH * CH, nullptr, nullptr,
        (__nv_bfloat16*)Mp, nullptr, nullptr,
        out, nullptr, nullptr, bp);
}

// round 15
// speedup vs baseline: 1.0535x; 1.0144x over previous
#include <cuda_runtime.h>
#include <cuda_bf16.h>
#include <cstdint>
#include <cmath>

#define BATCH 8
#define CH    512
#define NTOK  4096

// Blocked interchange layout for Q/K/V/M:
//   idx(b,c,n) = b*CH*NTOK + (n>>5)*(CH*32) + c*32 + (n&31)
#define BLKSTR (CH * 32)

// ---------------- scratch (device globals) ----------------
__device__ __nv_bfloat16 g_Wt[4 * CH * CH];           // transposed bf16 weights [c][d]
__device__ __nv_bfloat16 g_X [3 * BATCH * CH * NTOK]; // bf16 q,k,v in [b][c][n]
__device__ __nv_bfloat16 g_Q [BATCH * CH * NTOK];     // blocked layout
__device__ __nv_bfloat16 g_K [BATCH * CH * NTOK];     // blocked layout
__device__ __nv_bfloat16 g_V [BATCH * CH * NTOK];     // blocked layout
__device__ __nv_bfloat16 g_M [BATCH * CH * NTOK];     // blocked layout
__device__ float g_Ksum[BATCH * CH];

// ---------------- helpers ----------------
__device__ __forceinline__ uint32_t smem_u32(const void* p) {
    uint32_t a;
    asm("{ .reg .u64 t; cvta.to.shared.u64 t, %1; cvt.u32.u64 %0, t; }" : "=r"(a) : "l"(p));
    return a;
}
__device__ __forceinline__ uint32_t bf2u(__nv_bfloat162 h) {
    union { __nv_bfloat162 h; uint32_t u; } z; z.h = h; return z.u;
}
__device__ __forceinline__ void mma_bf16(float c[4], const uint32_t a[4], const uint32_t b[2]) {
    asm volatile(
        "mma.sync.aligned.m16n8k16.row.col.f32.bf16.bf16.f32 "
        "{%0,%1,%2,%3}, {%4,%5,%6,%7}, {%8,%9}, {%0,%1,%2,%3};"
        : "+f"(c[0]), "+f"(c[1]), "+f"(c[2]), "+f"(c[3])
        : "r"(a[0]), "r"(a[1]), "r"(a[2]), "r"(a[3]), "r"(b[0]), "r"(b[1]));
}
__device__ __forceinline__ void ldsm_x4(uint32_t r[4], uint32_t addr) {
    asm volatile("ldmatrix.sync.aligned.m8n8.x4.shared.b16 {%0,%1,%2,%3}, [%4];"
                 : "=r"(r[0]), "=r"(r[1]), "=r"(r[2]), "=r"(r[3]) : "r"(addr));
}
__device__ __forceinline__ void ldsm_x4_t(uint32_t r[4], uint32_t addr) {
    asm volatile("ldmatrix.sync.aligned.m8n8.x4.trans.shared.b16 {%0,%1,%2,%3}, [%4];"
                 : "=r"(r[0]), "=r"(r[1]), "=r"(r[2]), "=r"(r[3]) : "r"(addr));
}
#define CP16(dst, src) \
    asm volatile("cp.async.cg.shared.global [%0], [%1], 16;" :: "r"(dst), "l"(src) : "memory")
#define CP_COMMIT() asm volatile("cp.async.commit_group;" ::: "memory")
#define CP_WAIT(n)  asm volatile("cp.async.wait_group %0;" :: "n"(n) : "memory")

// packed f32x2 ops (sm_100+ base PTX)
__device__ __forceinline__ void fma2(unsigned long long& acc,
                                     unsigned long long a, unsigned long long b) {
    asm("fma.rn.f32x2 %0, %1, %2, %0;" : "+l"(acc) : "l"(a), "l"(b));
}
__device__ __forceinline__ unsigned long long bfpair_f32x2(uint32_t v) {
    union { uint32_t u; __nv_bfloat162 h; } z; z.u = v;
    float2 f = __bfloat1622float2(z.h);
    unsigned long long r;
    asm("mov.b64 %0, {%1, %2};" : "=l"(r) : "f"(f.x), "f"(f.y));
    return r;
}
// pack two f32 -> bf16x2 (lo = a, hi = b)
__device__ __forceinline__ uint32_t packbf(float a, float b) {
    uint32_t r;
    asm("cvt.rn.bf16x2.f32 %0, %1, %2;" : "=r"(r) : "f"(b), "f"(a));
    return r;
}

// =====================================================================
// weight prep: W fp32 [d][c] -> bf16 [c][d]  (grid 16,16,4); also zeros g_Ksum
// =====================================================================
__global__ __launch_bounds__(256) void wprep(
    const float* __restrict__ W0, const float* __restrict__ W1,
    const float* __restrict__ W2, const float* __restrict__ W3,
    __nv_bfloat16* __restrict__ D)
{
    __shared__ float t[32][33];
    if (blockIdx.z == 0 && blockIdx.y == 0)
        g_Ksum[blockIdx.x * 256 + threadIdx.x] = 0.f;
    const int z = blockIdx.z;
    const float* S = (z == 0) ? W0 : (z == 1) ? W1 : (z == 2) ? W2 : W3;
    __nv_bfloat16* Dz = D + (size_t)z * CH * CH;
    const int d0 = blockIdx.x * 32, c0 = blockIdx.y * 32;
    const int x = threadIdx.x & 31, y = threadIdx.x >> 5;
#pragma unroll
    for (int i = 0; i < 4; i++)
        t[y + 8 * i][x] = S[(size_t)(d0 + y + 8 * i) * CH + c0 + x];
    __syncthreads();
    const int m2 = threadIdx.x & 15, r0 = threadIdx.x >> 4;
#pragma unroll
    for (int i = 0; i < 2; i++) {
        const int r = r0 + 16 * i;
        __nv_bfloat162 h = __float22bfloat162_rn(make_float2(t[m2 * 2][r], t[m2 * 2 + 1][r]));
        *(__nv_bfloat162*)&Dz[(size_t)(c0 + r) * CH + d0 + m2 * 2] = h;
    }
}

// =====================================================================
// input prep: fp32 -> bf16 elementwise (grid 8192,1,3)
// =====================================================================
__global__ __launch_bounds__(256) void xconv(
    const float4* __restrict__ s0, const float4* __restrict__ s1,
    const float4* __restrict__ s2, uint4* __restrict__ d)
{
    const int z = blockIdx.z;
    const float4* s = (z == 0) ? s0 : (z == 1) ? s1 : s2;
    uint4* dz = d + (size_t)z * (BATCH * CH * NTOK / 8);
    const size_t i = (size_t)blockIdx.x * 256 + threadIdx.x;
    float4 a = s[2 * i], b = s[2 * i + 1];
    uint4 o;
    o.x = bf2u(__float22bfloat162_rn(make_float2(a.x, a.y)));
    o.y = bf2u(__float22bfloat162_rn(make_float2(a.z, a.w)));
    o.z = bf2u(__float22bfloat162_rn(make_float2(b.x, b.y)));
    o.w = bf2u(__float22bfloat162_rn(make_float2(b.z, b.w)));
    dz[i] = o;
}

// =====================================================================
// GEMM: C[b,d,n] = sum_c At[c,d] * B[b,c,n]  (+elu+1 | +bias | +ksum atomics)
// BM=BN=128, BK=32, 4-stage cp.async, 256 thr, 8 warps (4m x 2n), 32x64.
// PROJ: B token-major [c][n], C bf16 BLOCKED. !PROJ: B bf16 BLOCKED, C fp32 [c][n].
// =====================================================================
#define STG_SZ 16384
#define GEMM_SMEM (4 * STG_SZ)

template<bool PROJ, typename OutT, bool BIAS>
__global__ __launch_bounds__(256, 2) void gemm_ca(
    const __nv_bfloat16* __restrict__ A0, const __nv_bfloat16* __restrict__ A1,
    const __nv_bfloat16* __restrict__ A2,
    const __nv_bfloat16* __restrict__ X0, const __nv_bfloat16* __restrict__ X1,
    const __nv_bfloat16* __restrict__ X2,
    void* C0, void* C1, void* C2, const float* __restrict__ bias)
{
    extern __shared__ char smem[];
    const uint32_t sb = smem_u32(smem);

    int b; bool elu; int which = 0;
    const __nv_bfloat16 *A, *B; OutT* C;
    if (PROJ) {
        which = blockIdx.z >> 3; b = blockIdx.z & 7;
        A = (which == 0) ? A0 : (which == 1) ? A1 : A2;
        B = (which == 0) ? X0 : (which == 1) ? X1 : X2;
        C = (OutT*)((which == 0) ? C0 : (which == 1) ? C1 : C2);
        elu = (which < 2);
    } else {
        b = blockIdx.z; A = A0; B = X0; C = (OutT*)C0; elu = false;
    }

    const int m0 = blockIdx.y * 128, n0 = blockIdx.x * 128;
    const __nv_bfloat16* Bb = B + (size_t)b * CH * NTOK;
    OutT* Cb = C + (size_t)b * CH * NTOK;

    const int tid = threadIdx.x;
    const int lane = tid & 31, wid = tid >> 5;
    const int wm = wid & 3, wn = wid >> 2;
    const int gr = lane >> 2, kc = lane & 3;

    const int lr = tid >> 3;
    const int lc = (tid & 7) * 2;
    const int swz = lr & 7;

    const int klow = ((lane >> 3) & 1) * 8 + (lane & 7);
    const int cg   = lane >> 4;

    float acc[2][8][4];
#pragma unroll
    for (int i = 0; i < 2; i++)
#pragma unroll
        for (int j = 0; j < 8; j++)
#pragma unroll
            for (int r = 0; r < 4; r++) acc[i][j][r] = 0.f;

    auto issue = [&](int kt, int s) {
        const __nv_bfloat16* pa = A + (size_t)(kt * 32 + lr) * CH + m0 + lc * 8;
        const __nv_bfloat16* pb;
        if (PROJ) {
            pb = Bb + (size_t)(kt * 32 + lr) * NTOK + n0 + lc * 8;
        } else {
            const int tok = n0 + lc * 8;
            pb = Bb + (size_t)(tok >> 5) * BLKSTR + (size_t)(kt * 32 + lr) * 32 + (tok & 31);
        }
        const uint32_t base = sb + s * STG_SZ + lr * 256;
        CP16(base + ((lc     ^ swz) * 16),        pa);
        CP16(base + (((lc+1) ^ swz) * 16),        pa + 8);
        CP16(base + ((lc     ^ swz) * 16) + 8192, pb);
        CP16(base + (((lc+1) ^ swz) * 16) + 8192, pb + 8);
    };

#pragma unroll
    for (int s = 0; s < 3; s++) { issue(s, s); CP_COMMIT(); }

    const int KT = CH / 32;  // 16
#pragma unroll 1
    for (int kt = 0; kt < KT; ++kt) {
        CP_WAIT(2);
        __syncthreads();
        const int s = kt & 3;
        const uint32_t stA = sb + s * STG_SZ;

#pragma unroll
        for (int ks = 0; ks < 2; ++ks) {
            const int krow = ks * 16 + klow;
            const int kx = krow & 7;
            const uint32_t rb = stA + krow * 256;

            uint32_t af[2][4];
#pragma unroll
            for (int i = 0; i < 2; i++) {
                const int mc = wm * 4 + i * 2 + cg;
                uint32_t r[4];
                ldsm_x4_t(r, rb + ((mc ^ kx) * 16));
                af[i][0] = r[0]; af[i][1] = r[2]; af[i][2] = r[1]; af[i][3] = r[3];
            }
            uint32_t bf[8][2];
#pragma unroll
            for (int jj = 0; jj < 4; jj++) {
                const int nc = wn * 8 + jj * 2 + cg;
                uint32_t r[4];
                ldsm_x4_t(r, rb + 8192 + ((nc ^ kx) * 16));
                bf[jj * 2][0]     = r[0];
                bf[jj * 2][1]     = r[1];
                bf[jj * 2 + 1][0] = r[2];
                bf[jj * 2 + 1][1] = r[3];
            }
#pragma unroll
            for (int i = 0; i < 2; i++)
#pragma unroll
                for (int j = 0; j < 8; j++)
                    mma_bf16(acc[i][j], af[i], bf[j]);
        }

        if (kt + 3 < KT) issue(kt + 3, (kt + 3) & 3);
        CP_COMMIT();
    }

    // epilogue (+ fused Ksum for which==1)
#pragma unroll
    for (int i = 0; i < 2; i++) {
        const int row = m0 + wm * 32 + i * 16 + gr;
        const float bi0 = BIAS ? bias[row] : 0.f;
        const float bi1 = BIAS ? bias[row + 8] : 0.f;
        float rs0 = 0.f, rs1 = 0.f;
#pragma unroll
        for (int j = 0; j < 8; j++) {
            const int col = n0 + wn * 64 + j * 8 + kc * 2;
            float c0 = acc[i][j][0], c1 = acc[i][j][1];
            float c2 = acc[i][j][2], c3 = acc[i][j][3];
            if (PROJ && elu) {
                c0 = (c0 > 0.f) ? (c0 + 1.f) : __expf(c0);
                c1 = (c1 > 0.f) ? (c1 + 1.f) : __expf(c1);
                c2 = (c2 > 0.f) ? (c2 + 1.f) : __expf(c2);
                c3 = (c3 > 0.f) ? (c3 + 1.f) : __expf(c3);
            }
            if (BIAS) { c0 += bi0; c1 += bi0; c2 += bi1; c3 += bi1; }
            if (PROJ && which == 1) { rs0 += c0 + c1; rs1 += c2 + c3; }
            if constexpr (sizeof(OutT) == 2) {
                // blocked bf16 writes
                const size_t bbase = (size_t)(col >> 5) * BLKSTR + (col & 31);
                *(__nv_bfloat162*)&Cb[bbase + (size_t)row * 32] =
                    __float22bfloat162_rn(make_float2(c0, c1));
                *(__nv_bfloat162*)&Cb[bbase + (size_t)(row + 8) * 32] =
                    __float22bfloat162_rn(make_float2(c2, c3));
            } else {
                *(float2*)&Cb[(size_t)row * NTOK + col]       = make_float2(c0, c1);
                *(float2*)&Cb[(size_t)(row + 8) * NTOK + col] = make_float2(c2, c3);
            }
        }
        if (PROJ && which == 1) {
            rs0 += __shfl_xor_sync(0xffffffffu, rs0, 1);
            rs0 += __shfl_xor_sync(0xffffffffu, rs0, 2);
            rs1 += __shfl_xor_sync(0xffffffffu, rs1, 1);
            rs1 += __shfl_xor_sync(0xffffffffu, rs1, 2);
            if (kc == 0) {
                atomicAdd(&g_Ksum[b * CH + row],     rs0);
                atomicAdd(&g_Ksum[b * CH + row + 8], rs1);
            }
        }
    }
}

// =====================================================================
// Middle stage, tensor-core edition v6: 32 tokens/block, 1024 threads.
// Q/K/V/M in BLOCKED layout: one 32-token block = contiguous 32KB per
// tensor -> warp loads/stores are 512B contiguous (nL=4).
// Smem layouts / MMA core identical to validated v5.
// =====================================================================
#define QK_STR 80
#define QK_TOK 1280
#define VT_STR 48
#define VT_TOK 1536
#define GRP5   32800          // Q(10240)+K(10240)+V(12288) + 32B pad
#define GOFF_K 10240
#define GOFF_V 20480
#define OARENA (4 * GRP5)                 // 131200
#define OSTR   9248                       // 9216 + 32B pad
#define OFF_Z  (OARENA + 4 * OSTR)        // 168192
#define OFF_KS (OFF_Z + 32 * 17 * 4)      // 170368
#define MID_SMEM (OFF_KS + 16 * 36 * 4)   // 172672

__device__ __forceinline__ int sigma_o(int c2) {
    return (c2 & 3) | (((c2 >> 4) & 7) << 2) | (((c2 >> 2) & 3) << 5) | (((c2 >> 7) & 1) << 7);
}

__global__ __launch_bounds__(1024) void mid_kernel()
{
    extern __shared__ char smraw[];
    const uint32_t sb = smem_u32(smraw);
    float* Zs  = (float*)(smraw + OFF_Z);
    float* Ksm = (float*)(smraw + OFF_KS);

    const int blk = blockIdx.x;              // BATCH * 128
    const int b   = blk >> 7;
    const int nb  = blk & 127;               // 32-token block index
    const size_t reg = (size_t)b * CH * NTOK + (size_t)nb * BLKSTR;
    const int tid = threadIdx.x;
    const int l   = tid & 31;
    const int w   = tid >> 5;                // 0..31

    // ---- load phase (blocked gmem: fully coalesced) ----
    {
        const int s  = l >> 2;               // 0..7
        const int hh = l & 3;                // token group (tokens hh*8 .. hh*8+7)
        char* grp = smraw + hh * GRP5;

        const int c2 = w * 8 + s;
        uint4 qa = *(const uint4*)&g_Q[reg + (size_t)(2 * c2)     * 32 + hh * 8];
        uint4 qb = *(const uint4*)&g_Q[reg + (size_t)(2 * c2 + 1) * 32 + hh * 8];
        uint4 ka = *(const uint4*)&g_K[reg + (size_t)(2 * c2)     * 32 + hh * 8];
        uint4 kb = *(const uint4*)&g_K[reg + (size_t)(2 * c2 + 1) * 32 + hh * 8];
        const uint32_t qaw[4] = {qa.x, qa.y, qa.z, qa.w};
        const uint32_t qbw[4] = {qb.x, qb.y, qb.z, qb.w};
        const uint32_t kaw[4] = {ka.x, ka.y, ka.z, ka.w};
        const uint32_t kbw[4] = {kb.x, kb.y, kb.z, kb.w};
        const int hq  = c2 >> 4;
        const int d2m = c2 & 15;
        const int off = hq * QK_STR + d2m * 4;
#pragma unroll
        for (int j = 0; j < 4; j++) {
            uint32_t qe = __byte_perm(qaw[j], qbw[j], 0x5410);
            uint32_t qo = __byte_perm(qaw[j], qbw[j], 0x7632);
            uint32_t ke = __byte_perm(kaw[j], kbw[j], 0x5410);
            uint32_t ko = __byte_perm(kaw[j], kbw[j], 0x7632);
            *(uint32_t*)(grp + (2 * j)     * QK_TOK + off) = qe;
            *(uint32_t*)(grp + (2 * j + 1) * QK_TOK + off) = qo;
            *(uint32_t*)(grp + GOFF_K + (2 * j)     * QK_TOK + off) = ke;
            *(uint32_t*)(grp + GOFF_K + (2 * j + 1) * QK_TOK + off) = ko;
        }

        // V: rows (h2*64 + dv, +32); h2 = w>>2, dv = (w&3)*8 + s
        const int h2 = w >> 2;
        const int dv = ((w & 3) << 3) | s;
        uint4 va = *(const uint4*)&g_V[reg + (size_t)(h2 * 64 + dv)      * 32 + hh * 8];
        uint4 vb = *(const uint4*)&g_V[reg + (size_t)(h2 * 64 + dv + 32) * 32 + hh * 8];
        const uint32_t vaw[4] = {va.x, va.y, va.z, va.w};
        const uint32_t vbw[4] = {vb.x, vb.y, vb.z, vb.w};
        const int voff = dv * VT_STR + h2 * 4;
#pragma unroll
        for (int j = 0; j < 4; j++) {
            uint32_t ve = __byte_perm(vaw[j], vbw[j], 0x5410);
            uint32_t vo = __byte_perm(vaw[j], vbw[j], 0x7632);
            *(uint32_t*)(grp + GOFF_V + (2 * j)     * VT_TOK + voff) = ve;
            *(uint32_t*)(grp + GOFF_V + (2 * j + 1) * VT_TOK + voff) = vo;
        }

        if (tid < CH)
            Ksm[(tid >> 5) * 36 + (tid & 31)] = g_Ksum[b * CH + tid];
    }
    __syncthreads();

    // ---- MMA phase: warp w = token w; group g = w>>3, slot = w&7 ----
    const int g    = w >> 3;
    const int slot = w & 7;
    const int row  = l & 15;
    const int half = l >> 4;
    const int gr   = l >> 2, kc = l & 3;

    const uint32_t gb  = sb + g * GRP5;
    const uint32_t qb_ = gb + slot * QK_TOK;
    const uint32_t kb_ = gb + GOFF_K + slot * QK_TOK;
    const uint32_t vb_ = gb + GOFF_V + slot * VT_TOK;

    uint32_t aQ0[4], aQ1[4], kf0[4], kf1[4];
    ldsm_x4(aQ0, qb_ + row * QK_STR + half * 16);
    ldsm_x4(aQ1, qb_ + row * QK_STR + 32 + half * 16);
    ldsm_x4(kf0, kb_ + row * QK_STR + half * 16);
    ldsm_x4(kf1, kb_ + row * QK_STR + 32 + half * 16);

    float S0[4] = {0.f, 0.f, 0.f, 0.f};
    float S1[4] = {0.f, 0.f, 0.f, 0.f};
    {
        uint32_t bb[2];
        bb[0] = kf0[0]; bb[1] = kf0[2]; mma_bf16(S0, aQ0, bb);
        bb[0] = kf0[1]; bb[1] = kf0[3]; mma_bf16(S1, aQ0, bb);
        bb[0] = kf1[0]; bb[1] = kf1[2]; mma_bf16(S0, aQ1, bb);
        bb[0] = kf1[1]; bb[1] = kf1[3]; mma_bf16(S1, aQ1, bb);
    }

    // Z: lanes 0..15, h = lane
    if (l < 16) {
        unsigned long long acc = 0;
        const int h = l;
#pragma unroll
        for (int d2 = 0; d2 < 16; d2++) {
            uint32_t qp;
            asm volatile("ld.shared.b32 %0, [%1];" : "=r"(qp)
                         : "r"(qb_ + h * QK_STR + d2 * 4));
            unsigned long long kq = *(const unsigned long long*)(Ksm + h * 36 + 2 * d2);
            fma2(acc, bfpair_f32x2(qp), kq);
        }
        float x, y;
        asm("mov.b64 {%0, %1}, %2;" : "=f"(x), "=f"(y) : "l"(acc));
        Zs[w * 17 + h] = 1.f / (x + y + 1e-5f);
    }

    // S -> A2 fragments (accumulator layout == A-operand layout)
    uint32_t a2[4];
    a2[0] = packbf(S0[0], S0[1]);
    a2[1] = packbf(S0[2], S0[3]);
    a2[2] = packbf(S1[0], S1[1]);
    a2[3] = packbf(S1[2], S1[3]);

    uint32_t vf0[4], vf1[4];
    ldsm_x4(vf0, vb_ + row * VT_STR + half * 16);
    ldsm_x4(vf1, vb_ + (16 + row) * VT_STR + half * 16);

    float O[4][4];
#pragma unroll
    for (int gg = 0; gg < 4; gg++)
#pragma unroll
        for (int r = 0; r < 4; r++) O[gg][r] = 0.f;
    {
        uint32_t bb[2];
        bb[0] = vf0[0]; bb[1] = vf0[2]; mma_bf16(O[0], a2, bb);
        bb[0] = vf0[1]; bb[1] = vf0[3]; mma_bf16(O[1], a2, bb);
        bb[0] = vf1[0]; bb[1] = vf1[2]; mma_bf16(O[2], a2, bb);
        bb[0] = vf1[1]; bb[1] = vf1[3]; mma_bf16(O[3], a2, bb);
    }

    __syncwarp();
    const float zlo = Zs[w * 17 + gr];
    const float zhi = Zs[w * 17 + gr + 8];
#pragma unroll
    for (int gg = 0; gg < 4; gg++) {
        const int c2a = gr * 16 + gg * 4 + kc;
        const int c2b = (gr + 8) * 16 + gg * 4 + kc;
        uint32_t wlo = packbf(O[gg][0] * zlo, O[gg][1] * zlo);
        uint32_t whi = packbf(O[gg][2] * zhi, O[gg][3] * zhi);
        *(uint32_t*)(smraw + OARENA + g * OSTR + (sigma_o(c2a) * 9 + slot) * 4) = wlo;
        *(uint32_t*)(smraw + OARENA + g * OSTR + (sigma_o(c2b) * 9 + slot) * 4) = whi;
    }
    __syncthreads();

    // ---- store phase (blocked gmem: fully coalesced) ----
    {
        const int s2 = l >> 2;               // 0..7
        const int tg = l & 3;                // token group
        const int c2 = w * 8 + s2;           // 0..255
        const uint32_t ob = (uint32_t)(OARENA + tg * OSTR) +
                            (uint32_t)(sigma_o(c2) * 9) * 4;
        uint32_t ww[8];
#pragma unroll
        for (int tt = 0; tt < 8; tt++)
            ww[tt] = *(const uint32_t*)(smraw + ob + tt * 4);
        uint4 lo, hi;
        lo.x = __byte_perm(ww[0], ww[1], 0x5410);
        lo.y = __byte_perm(ww[2], ww[3], 0x5410);
        lo.z = __byte_perm(ww[4], ww[5], 0x5410);
        lo.w = __byte_perm(ww[6], ww[7], 0x5410);
        hi.x = __byte_perm(ww[0], ww[1], 0x7632);
        hi.y = __byte_perm(ww[2], ww[3], 0x7632);
        hi.z = __byte_perm(ww[4], ww[5], 0x7632);
        hi.w = __byte_perm(ww[6], ww[7], 0x7632);
        *(uint4*)&g_M[reg + (size_t)(2 * c2)     * 32 + tg * 8] = lo;
        *(uint4*)&g_M[reg + (size_t)(2 * c2 + 1) * 32 + tg * 8] = hi;
    }
}

// =====================================================================
extern "C" void kernel_launch(void* const* d_in, const int* in_sizes, int n_in,
                              void* d_out, int out_size)
{
    (void)in_sizes; (void)n_in; (void)out_size;
    const float* q  = (const float*)d_in[0];
    const float* k  = (const float*)d_in[1];
    const float* v  = (const float*)d_in[2];
    const float* Wq = (const float*)d_in[3];
    const float* Wk = (const float*)d_in[4];
    const float* Wv = (const float*)d_in[5];
    const float* Wp = (const float*)d_in[6];
    const float* bp = (const float*)d_in[7];
    float* out = (float*)d_out;

    void *wt, *x, *Qp, *Kp, *Vp, *Mp;
    cudaGetSymbolAddress(&wt, g_Wt);
    cudaGetSymbolAddress(&x,  g_X);
    cudaGetSymbolAddress(&Qp, g_Q);
    cudaGetSymbolAddress(&Kp, g_K);
    cudaGetSymbolAddress(&Vp, g_V);
    cudaGetSymbolAddress(&Mp, g_M);
    __nv_bfloat16* Wt = (__nv_bfloat16*)wt;
    __nv_bfloat16* X  = (__nv_bfloat16*)x;
    const size_t XS = (size_t)BATCH * CH * NTOK;

    cudaFuncSetAttribute(gemm_ca<true,  __nv_bfloat16, false>,
                         cudaFuncAttributeMaxDynamicSharedMemorySize, GEMM_SMEM);
    cudaFuncSetAttribute(gemm_ca<false, float, true>,
                         cudaFuncAttributeMaxDynamicSharedMemorySize, GEMM_SMEM);
    cudaFuncSetAttribute(mid_kernel,
                         cudaFuncAttributeMaxDynamicSharedMemorySize, MID_SMEM);

    // 1. prep (wprep also zeroes g_Ksum)
    wprep<<<dim3(16, 16, 4), 256>>>(Wq, Wk, Wv, Wp, Wt);
    xconv<<<dim3(8192, 1, 3), 256>>>((const float4*)q, (const float4*)k,
                                     (const float4*)v, (uint4*)X);

    // 2. projections (fused 3-in-1; K-proj accumulates Ksum via atomics)
    dim3 gp(NTOK / 128, CH / 128, 3 * BATCH);
    gemm_ca<true, __nv_bfloat16, false><<<gp, 256, GEMM_SMEM>>>(
        Wt, Wt + CH * CH, Wt + 2 * CH * CH,
        X, X + XS, X + 2 * XS,
        Qp, Kp, Vp, nullptr);

    // 3. middle (tensor-core, 32 tokens/block, blocked I/O)
    mid_kernel<<<BATCH * (NTOK / 32), 1024, MID_SMEM>>>();

    // 4. output projection (B = blocked g_M)
    dim3 gf(NTOK / 128, CH / 128, BATCH);
    gemm_ca<false, float, true><<<gf, 256, GEMM_SMEM>>>(
        Wt + 3 * CH * CH, nullptr, nullptr,
        (__nv_bfloat16*)Mp, nullptr, nullptr,
        out, nullptr, nullptr, bp);
}